// round 11
// baseline (speedup 1.0000x reference)
#include <cuda_runtime.h>
#include <cstdint>

// ---------------------------------------------------------------------------
// EigenGIN: 3x GIN layer (CSR gather segment-sum + fused MLP) + projection
// fused into the last MLP. f32x2 packed FMA everywhere hot.
// ---------------------------------------------------------------------------

#define MAX_EDGES 800000
#define MAX_NODES_PAD 50048   // multiple of 128 (GEMM BM)
#define EMBED 128

__device__ int   g_col [MAX_EDGES];
__device__ int   g_deg [MAX_NODES_PAD];
__device__ int   g_rowptr[MAX_NODES_PAD + 1];
__device__ int   g_cursor[MAX_NODES_PAD];
__device__ float g_pre [(size_t)MAX_NODES_PAD * EMBED];
__device__ float g_bufA[(size_t)MAX_NODES_PAD * EMBED];
__device__ float g_bufB[(size_t)MAX_NODES_PAD * EMBED];

// dtype probe: true int64 edge indices (<5e4) have zero high words.
__device__ __forceinline__ int detect_is64(const void* edges, int n_edges) {
    const long long* p = (const long long*)edges;
    int lim = n_edges < 64 ? n_edges : 64;
    for (int i = 0; i < lim; i++)
        if ((p[i] >> 32) != 0) return 0;
    return 1;
}

// ------------------------------------------------- histogram of dst degrees
__global__ void k_hist(const void* __restrict__ edges, int n_edges) {
    __shared__ int s_is64;
    if (threadIdx.x == 0) s_is64 = detect_is64(edges, n_edges);
    __syncthreads();
    const int is64 = s_is64;
    for (int e = blockIdx.x * blockDim.x + threadIdx.x; e < n_edges;
         e += gridDim.x * blockDim.x) {
        int d = is64 ? (int)((const long long*)edges)[e + n_edges]
                     : ((const int*)edges)[e + n_edges];
        atomicAdd(&g_deg[d], 1);
    }
}

// ------------------------------------------------ single-block exclusive scan
__global__ void k_scan(int n) {
    __shared__ int sh[1024];
    const int tid = threadIdx.x;
    const int chunk = (n + 1023) / 1024;
    const int lo = tid * chunk;
    const int hi = min(lo + chunk, n);
    int local = 0;
    for (int i = lo; i < hi; i++) local += g_deg[i];
    sh[tid] = local;
    __syncthreads();
    for (int off = 1; off < 1024; off <<= 1) {
        int v = (tid >= off) ? sh[tid - off] : 0;
        __syncthreads();
        sh[tid] += v;
        __syncthreads();
    }
    int run = sh[tid] - local;
    for (int i = lo; i < hi; i++) {
        g_rowptr[i] = run;
        g_cursor[i] = run;
        run += g_deg[i];
    }
    if (tid == 1023) g_rowptr[n] = sh[1023];
}

// ------------------------------------------------------------- scatter cols
__global__ void k_scatter(const void* __restrict__ edges, int n_edges) {
    __shared__ int s_is64;
    if (threadIdx.x == 0) s_is64 = detect_is64(edges, n_edges);
    __syncthreads();
    const int is64 = s_is64;
    for (int e = blockIdx.x * blockDim.x + threadIdx.x; e < n_edges;
         e += gridDim.x * blockDim.x) {
        int s, d;
        if (is64) {
            const long long* p = (const long long*)edges;
            s = (int)p[e];
            d = (int)p[e + n_edges];
        } else {
            const int* p = (const int*)edges;
            s = p[e];
            d = p[e + n_edges];
        }
        int pos = atomicAdd(&g_cursor[d], 1);
        g_col[pos] = s;
    }
}

// ------------------------------------------- aggregation: pre[i] = x[i]+sum
template <int D>
__global__ void __launch_bounds__(256)
k_agg(const float* __restrict__ X, float* __restrict__ pre, int n) {
    constexpr int G = D / 4;
    const int node = (blockIdx.x * blockDim.x + threadIdx.x) / G;
    const int lane = threadIdx.x & (G - 1);
    if (node >= n) return;
    const float4* X4 = (const float4*)X;
    float4 a0 = X4[(size_t)node * G + lane];
    float4 a1 = make_float4(0.f, 0.f, 0.f, 0.f);
    float4 a2 = make_float4(0.f, 0.f, 0.f, 0.f);
    float4 a3 = make_float4(0.f, 0.f, 0.f, 0.f);
    const int s = g_rowptr[node];
    const int e = g_rowptr[node + 1];
    int k = s;
    for (; k + 8 <= e; k += 8) {
        int j0 = __ldg(&g_col[k]);
        int j1 = __ldg(&g_col[k + 1]);
        int j2 = __ldg(&g_col[k + 2]);
        int j3 = __ldg(&g_col[k + 3]);
        int j4 = __ldg(&g_col[k + 4]);
        int j5 = __ldg(&g_col[k + 5]);
        int j6 = __ldg(&g_col[k + 6]);
        int j7 = __ldg(&g_col[k + 7]);
        float4 v0 = X4[(size_t)j0 * G + lane];
        float4 v1 = X4[(size_t)j1 * G + lane];
        float4 v2 = X4[(size_t)j2 * G + lane];
        float4 v3 = X4[(size_t)j3 * G + lane];
        float4 v4 = X4[(size_t)j4 * G + lane];
        float4 v5 = X4[(size_t)j5 * G + lane];
        float4 v6 = X4[(size_t)j6 * G + lane];
        float4 v7 = X4[(size_t)j7 * G + lane];
        a0.x += v0.x; a0.y += v0.y; a0.z += v0.z; a0.w += v0.w;
        a1.x += v1.x; a1.y += v1.y; a1.z += v1.z; a1.w += v1.w;
        a2.x += v2.x; a2.y += v2.y; a2.z += v2.z; a2.w += v2.w;
        a3.x += v3.x; a3.y += v3.y; a3.z += v3.z; a3.w += v3.w;
        a0.x += v4.x; a0.y += v4.y; a0.z += v4.z; a0.w += v4.w;
        a1.x += v5.x; a1.y += v5.y; a1.z += v5.z; a1.w += v5.w;
        a2.x += v6.x; a2.y += v6.y; a2.z += v6.z; a2.w += v6.w;
        a3.x += v7.x; a3.y += v7.y; a3.z += v7.z; a3.w += v7.w;
    }
    for (; k + 4 <= e; k += 4) {
        int j0 = __ldg(&g_col[k]);
        int j1 = __ldg(&g_col[k + 1]);
        int j2 = __ldg(&g_col[k + 2]);
        int j3 = __ldg(&g_col[k + 3]);
        float4 v0 = X4[(size_t)j0 * G + lane];
        float4 v1 = X4[(size_t)j1 * G + lane];
        float4 v2 = X4[(size_t)j2 * G + lane];
        float4 v3 = X4[(size_t)j3 * G + lane];
        a0.x += v0.x; a0.y += v0.y; a0.z += v0.z; a0.w += v0.w;
        a1.x += v1.x; a1.y += v1.y; a1.z += v1.z; a1.w += v1.w;
        a2.x += v2.x; a2.y += v2.y; a2.z += v2.z; a2.w += v2.w;
        a3.x += v3.x; a3.y += v3.y; a3.z += v3.z; a3.w += v3.w;
    }
    for (; k < e; k++) {
        int j = __ldg(&g_col[k]);
        float4 v = X4[(size_t)j * G + lane];
        a0.x += v.x; a0.y += v.y; a0.z += v.z; a0.w += v.w;
    }
    a0.x += a1.x + a2.x + a3.x;
    a0.y += a1.y + a2.y + a3.y;
    a0.z += a1.z + a2.z + a3.z;
    a0.w += a1.w + a2.w + a3.w;
    ((float4*)pre)[(size_t)node * G + lane] = a0;
}

// --------------------- fused GEMM (N=128) + optional fused 128->32 projection
// BM=128, 256 threads, TM=8 x TN=8, f32x2 packed FMA. When PROJ, the h tile
// never touches gmem: staged through smem chunks and projected in-block.
template <int K, bool PROJ>
__global__ void __launch_bounds__(256)
k_mlp128(const float* __restrict__ Pre, const float* __restrict__ W,
         const float* __restrict__ bias, const float* __restrict__ resid,
         float* __restrict__ out, int n, int do_relu,
         const float* __restrict__ Wp, const float* __restrict__ bp,
         float* __restrict__ outP) {
    constexpr int N = 128, BM = 128, KT = 32, TM = 8;
    constexpr int ASS = BM + 4;
    __shared__ float As[KT * ASS];              // transposed: As[k][m]
    __shared__ float Ws[KT * N];
    __shared__ float bpS[32];
    const int tid = threadIdx.x;                // 256
    const int tx = tid & 15;
    const int ty = tid >> 4;
    const int m0 = blockIdx.x * BM;

    unsigned long long acc[TM][4];
#pragma unroll
    for (int i = 0; i < TM; i++)
#pragma unroll
        for (int j = 0; j < 4; j++) acc[i][j] = 0ULL;

    for (int k0 = 0; k0 < K; k0 += KT) {
        for (int i = tid; i < BM * (KT / 4); i += 256) {
            int row = i / (KT / 4), kf = i % (KT / 4);
            float4 v = *(const float4*)&Pre[(size_t)(m0 + row) * K + k0 + kf * 4];
            int kb = kf * 4;
            As[(kb + 0) * ASS + row] = v.x;
            As[(kb + 1) * ASS + row] = v.y;
            As[(kb + 2) * ASS + row] = v.z;
            As[(kb + 3) * ASS + row] = v.w;
        }
        for (int i = tid; i < KT * (N / 4); i += 256) {
            int kk = i / (N / 4), cf = i % (N / 4);
            *(float4*)&Ws[kk * N + cf * 4] =
                *(const float4*)&W[(size_t)(k0 + kk) * N + cf * 4];
        }
        __syncthreads();
#pragma unroll
        for (int kk = 0; kk < KT; kk++) {
            float4 alo = *(const float4*)&As[kk * ASS + ty * TM];
            float4 ahi = *(const float4*)&As[kk * ASS + ty * TM + 4];
            float av[TM] = {alo.x, alo.y, alo.z, alo.w,
                            ahi.x, ahi.y, ahi.z, ahi.w};
            const ulonglong2* wp2 = (const ulonglong2*)&Ws[kk * N + tx * 8];
            ulonglong2 w01 = wp2[0];
            ulonglong2 w23 = wp2[1];
            unsigned long long bpk[4] = {w01.x, w01.y, w23.x, w23.y};
#pragma unroll
            for (int i = 0; i < TM; i++) {
                unsigned int ab = __float_as_uint(av[i]);
                unsigned long long ap;
                asm("mov.b64 %0, {%1, %2};" : "=l"(ap) : "r"(ab), "r"(ab));
#pragma unroll
                for (int j = 0; j < 4; j++) {
                    asm("fma.rn.f32x2 %0, %1, %2, %0;"
                        : "+l"(acc[i][j]) : "l"(ap), "l"(bpk[j]));
                }
            }
        }
        __syncthreads();
    }

    // epilogue: bias -> relu -> residual -> (store | fused projection)
    float hv[TM][8];
#pragma unroll
    for (int i = 0; i < TM; i++) {
        int row = m0 + ty * TM + i;
#pragma unroll
        for (int j = 0; j < 4; j++) {
            unsigned int lo, hi;
            asm("mov.b64 {%0, %1}, %2;" : "=r"(lo), "=r"(hi) : "l"(acc[i][j]));
            int col = tx * 8 + j * 2;
            float v0 = __uint_as_float(lo) + bias[col];
            float v1 = __uint_as_float(hi) + bias[col + 1];
            if (do_relu) { v0 = fmaxf(v0, 0.f); v1 = fmaxf(v1, 0.f); }
            if (resid) {                      // scratch arrays padded: safe
                v0 += resid[(size_t)row * N + col];
                v1 += resid[(size_t)row * N + col + 1];
            }
            hv[i][j * 2]     = v0;
            hv[i][j * 2 + 1] = v1;
        }
    }

    if (!PROJ) {
#pragma unroll
        for (int i = 0; i < TM; i++) {
            int row = m0 + ty * TM + i;
            if (row >= n) continue;
#pragma unroll
            for (int j = 0; j < 4; j++) {
                int col = tx * 8 + j * 2;
                out[(size_t)row * N + col]     = hv[i][j * 2];
                out[(size_t)row * N + col + 1] = hv[i][j * 2 + 1];
            }
        }
        return;
    }

    // ---- fused projection: outP[row] = h[row] @ Wp + bp  (128 -> 32) ----
    // Wp into Ws region (4096 floats, exact fit); h chunks through As region.
    for (int i = tid; i < 1024; i += 256)
        ((float4*)Ws)[i] = ((const float4*)Wp)[i];
    if (tid < 32) bpS[tid] = bp[tid];
    float* Hs = As;                         // 32 x ASS chunk

    const int prow = tid >> 3;              // 0..31  (chunk-local row)
    const int pcg  = tid & 7;               // col group: cols pcg*4..+3

#pragma unroll
    for (int rc = 0; rc < 4; rc++) {
        __syncthreads();                    // Ws/Hs ready; prior reads done
        if ((ty >> 2) == rc) {
            int rb = (ty & 3) * 8;
#pragma unroll
            for (int i = 0; i < TM; i++)
#pragma unroll
                for (int j = 0; j < 8; j++)
                    Hs[(rb + i) * ASS + tx * 8 + j] = hv[i][j];
        }
        __syncthreads();
        unsigned long long o01 = 0ULL, o23 = 0ULL;
#pragma unroll 8
        for (int col = 0; col < 128; col++) {
            unsigned int hb = __float_as_uint(Hs[prow * ASS + col]);
            unsigned long long hp;
            asm("mov.b64 %0, {%1, %2};" : "=l"(hp) : "r"(hb), "r"(hb));
            ulonglong2 w = *(const ulonglong2*)&Ws[col * 32 + pcg * 4];
            asm("fma.rn.f32x2 %0, %1, %2, %0;" : "+l"(o01) : "l"(hp), "l"(w.x));
            asm("fma.rn.f32x2 %0, %1, %2, %0;" : "+l"(o23) : "l"(hp), "l"(w.y));
        }
        int gRow = m0 + rc * 32 + prow;
        if (gRow < n) {
            unsigned int r0, r1, r2, r3;
            asm("mov.b64 {%0, %1}, %2;" : "=r"(r0), "=r"(r1) : "l"(o01));
            asm("mov.b64 {%0, %1}, %2;" : "=r"(r2), "=r"(r3) : "l"(o23));
            float4 res;
            res.x = __uint_as_float(r0) + bpS[pcg * 4];
            res.y = __uint_as_float(r1) + bpS[pcg * 4 + 1];
            res.z = __uint_as_float(r2) + bpS[pcg * 4 + 2];
            res.w = __uint_as_float(r3) + bpS[pcg * 4 + 3];
            *(float4*)&outP[(size_t)gRow * 32 + pcg * 4] = res;
        }
    }
}

// ---------------------------------------------------------------------------
extern "C" void kernel_launch(void* const* d_in, const int* in_sizes, int n_in,
                              void* d_out, int out_size) {
    const float* x  = (const float*)d_in[0];
    const void*  ei = d_in[1];
    const float* W0 = (const float*)d_in[2];
    const float* b0 = (const float*)d_in[3];
    const float* W1 = (const float*)d_in[4];
    const float* b1 = (const float*)d_in[5];
    const float* W2 = (const float*)d_in[6];
    const float* b2 = (const float*)d_in[7];
    const float* Wp = (const float*)d_in[8];
    const float* bp = (const float*)d_in[9];
    float* out = (float*)d_out;

    int n_nodes = in_sizes[0] / 64;          // IN_DIM = 64
    int n_edges = in_sizes[1] / 2;
    if (n_nodes > MAX_NODES_PAD) n_nodes = MAX_NODES_PAD;
    if (n_edges > MAX_EDGES)     n_edges = MAX_EDGES;

    float* pre;  cudaGetSymbolAddress((void**)&pre,  g_pre);
    float* bufA; cudaGetSymbolAddress((void**)&bufA, g_bufA);
    float* bufB; cudaGetSymbolAddress((void**)&bufB, g_bufB);
    int*   deg;  cudaGetSymbolAddress((void**)&deg,  g_deg);

    const int T = 256;
    cudaMemsetAsync(deg, 0, (size_t)n_nodes * sizeof(int));
    k_hist<<<(n_edges + T - 1) / T, T>>>(ei, n_edges);
    k_scan<<<1, 1024>>>(n_nodes);
    k_scatter<<<(n_edges + T - 1) / T, T>>>(ei, n_edges);

    const int agg64Blocks  = (n_nodes * 16 + 255) / 256;
    const int agg128Blocks = (n_nodes * 32 + 255) / 256;
    const int mlpBlocks    = (n_nodes + 127) / 128;

    // layer 0: 64 -> 128, relu
    k_agg<64><<<agg64Blocks, 256>>>(x, pre, n_nodes);
    k_mlp128<64, false><<<mlpBlocks, 256>>>(pre, W0, b0, nullptr, bufA,
                                            n_nodes, 1, nullptr, nullptr, nullptr);
    // layer 1: 128 -> 128, relu, residual bufA
    k_agg<128><<<agg128Blocks, 256>>>(bufA, pre, n_nodes);
    k_mlp128<128, false><<<mlpBlocks, 256>>>(pre, W1, b1, bufA, bufB,
                                             n_nodes, 1, nullptr, nullptr, nullptr);
    // layer 2 + fused projection: h2 = relu(pre@W2+b2)+bufB; out = h2@Wp+bp
    k_agg<128><<<agg128Blocks, 256>>>(bufB, pre, n_nodes);
    k_mlp128<128, true><<<mlpBlocks, 256>>>(pre, W2, b2, bufB, nullptr,
                                            n_nodes, 1, Wp, bp, out);
}

// round 15
// speedup vs baseline: 1.0987x; 1.0987x over previous
#include <cuda_runtime.h>
#include <cstdint>

// ---------------------------------------------------------------------------
// EigenGIN: 3x GIN layer (CSR gather segment-sum + fused MLP) + projection.
// MLP: double-buffered smem pipeline, f32x2 packed FMA.
// ---------------------------------------------------------------------------

#define MAX_EDGES 800000
#define MAX_NODES_PAD 50048   // multiple of 128 (GEMM BM)
#define EMBED 128

__device__ int   g_col [MAX_EDGES];
__device__ int   g_deg [MAX_NODES_PAD];
__device__ int   g_rowptr[MAX_NODES_PAD + 1];
__device__ int   g_cursor[MAX_NODES_PAD];
__device__ float g_pre [(size_t)MAX_NODES_PAD * EMBED];
__device__ float g_bufA[(size_t)MAX_NODES_PAD * EMBED];
__device__ float g_bufB[(size_t)MAX_NODES_PAD * EMBED];

// dtype probe: true int64 edge indices (<5e4) have zero high words.
__device__ __forceinline__ int detect_is64(const void* edges, int n_edges) {
    const long long* p = (const long long*)edges;
    int lim = n_edges < 64 ? n_edges : 64;
    for (int i = 0; i < lim; i++)
        if ((p[i] >> 32) != 0) return 0;
    return 1;
}

// ------------------------------------------------- histogram of dst degrees
__global__ void k_hist(const void* __restrict__ edges, int n_edges) {
    __shared__ int s_is64;
    if (threadIdx.x == 0) s_is64 = detect_is64(edges, n_edges);
    __syncthreads();
    const int is64 = s_is64;
    for (int e = blockIdx.x * blockDim.x + threadIdx.x; e < n_edges;
         e += gridDim.x * blockDim.x) {
        int d = is64 ? (int)((const long long*)edges)[e + n_edges]
                     : ((const int*)edges)[e + n_edges];
        atomicAdd(&g_deg[d], 1);
    }
}

// ------------------------------------------------ single-block exclusive scan
__global__ void k_scan(int n) {
    __shared__ int sh[1024];
    const int tid = threadIdx.x;
    const int chunk = (n + 1023) / 1024;
    const int lo = tid * chunk;
    const int hi = min(lo + chunk, n);
    int local = 0;
    for (int i = lo; i < hi; i++) local += g_deg[i];
    sh[tid] = local;
    __syncthreads();
    for (int off = 1; off < 1024; off <<= 1) {
        int v = (tid >= off) ? sh[tid - off] : 0;
        __syncthreads();
        sh[tid] += v;
        __syncthreads();
    }
    int run = sh[tid] - local;
    for (int i = lo; i < hi; i++) {
        g_rowptr[i] = run;
        g_cursor[i] = run;
        run += g_deg[i];
    }
    if (tid == 1023) g_rowptr[n] = sh[1023];
}

// ------------------------------------------------------------- scatter cols
__global__ void k_scatter(const void* __restrict__ edges, int n_edges) {
    __shared__ int s_is64;
    if (threadIdx.x == 0) s_is64 = detect_is64(edges, n_edges);
    __syncthreads();
    const int is64 = s_is64;
    for (int e = blockIdx.x * blockDim.x + threadIdx.x; e < n_edges;
         e += gridDim.x * blockDim.x) {
        int s, d;
        if (is64) {
            const long long* p = (const long long*)edges;
            s = (int)p[e];
            d = (int)p[e + n_edges];
        } else {
            const int* p = (const int*)edges;
            s = p[e];
            d = p[e + n_edges];
        }
        int pos = atomicAdd(&g_cursor[d], 1);
        g_col[pos] = s;
    }
}

// ------------------------------------------- aggregation: pre[i] = x[i]+sum
template <int D>
__global__ void __launch_bounds__(256)
k_agg(const float* __restrict__ X, float* __restrict__ pre, int n) {
    constexpr int G = D / 4;
    const int node = (blockIdx.x * blockDim.x + threadIdx.x) / G;
    const int lane = threadIdx.x & (G - 1);
    if (node >= n) return;
    const float4* X4 = (const float4*)X;
    float4 a0 = X4[(size_t)node * G + lane];
    float4 a1 = make_float4(0.f, 0.f, 0.f, 0.f);
    float4 a2 = make_float4(0.f, 0.f, 0.f, 0.f);
    float4 a3 = make_float4(0.f, 0.f, 0.f, 0.f);
    const int s = g_rowptr[node];
    const int e = g_rowptr[node + 1];
    int k = s;
    for (; k + 8 <= e; k += 8) {
        int j0 = __ldg(&g_col[k]);
        int j1 = __ldg(&g_col[k + 1]);
        int j2 = __ldg(&g_col[k + 2]);
        int j3 = __ldg(&g_col[k + 3]);
        int j4 = __ldg(&g_col[k + 4]);
        int j5 = __ldg(&g_col[k + 5]);
        int j6 = __ldg(&g_col[k + 6]);
        int j7 = __ldg(&g_col[k + 7]);
        float4 v0 = X4[(size_t)j0 * G + lane];
        float4 v1 = X4[(size_t)j1 * G + lane];
        float4 v2 = X4[(size_t)j2 * G + lane];
        float4 v3 = X4[(size_t)j3 * G + lane];
        float4 v4 = X4[(size_t)j4 * G + lane];
        float4 v5 = X4[(size_t)j5 * G + lane];
        float4 v6 = X4[(size_t)j6 * G + lane];
        float4 v7 = X4[(size_t)j7 * G + lane];
        a0.x += v0.x; a0.y += v0.y; a0.z += v0.z; a0.w += v0.w;
        a1.x += v1.x; a1.y += v1.y; a1.z += v1.z; a1.w += v1.w;
        a2.x += v2.x; a2.y += v2.y; a2.z += v2.z; a2.w += v2.w;
        a3.x += v3.x; a3.y += v3.y; a3.z += v3.z; a3.w += v3.w;
        a0.x += v4.x; a0.y += v4.y; a0.z += v4.z; a0.w += v4.w;
        a1.x += v5.x; a1.y += v5.y; a1.z += v5.z; a1.w += v5.w;
        a2.x += v6.x; a2.y += v6.y; a2.z += v6.z; a2.w += v6.w;
        a3.x += v7.x; a3.y += v7.y; a3.z += v7.z; a3.w += v7.w;
    }
    for (; k + 4 <= e; k += 4) {
        int j0 = __ldg(&g_col[k]);
        int j1 = __ldg(&g_col[k + 1]);
        int j2 = __ldg(&g_col[k + 2]);
        int j3 = __ldg(&g_col[k + 3]);
        float4 v0 = X4[(size_t)j0 * G + lane];
        float4 v1 = X4[(size_t)j1 * G + lane];
        float4 v2 = X4[(size_t)j2 * G + lane];
        float4 v3 = X4[(size_t)j3 * G + lane];
        a0.x += v0.x; a0.y += v0.y; a0.z += v0.z; a0.w += v0.w;
        a1.x += v1.x; a1.y += v1.y; a1.z += v1.z; a1.w += v1.w;
        a2.x += v2.x; a2.y += v2.y; a2.z += v2.z; a2.w += v2.w;
        a3.x += v3.x; a3.y += v3.y; a3.z += v3.z; a3.w += v3.w;
    }
    for (; k < e; k++) {
        int j = __ldg(&g_col[k]);
        float4 v = X4[(size_t)j * G + lane];
        a0.x += v.x; a0.y += v.y; a0.z += v.z; a0.w += v.w;
    }
    a0.x += a1.x + a2.x + a3.x;
    a0.y += a1.y + a2.y + a3.y;
    a0.z += a1.z + a2.z + a3.z;
    a0.w += a1.w + a2.w + a3.w;
    ((float4*)pre)[(size_t)node * G + lane] = a0;
}

// ------------------- stage one KT=16 tile of Pre (transposed) + W into smem
__device__ __forceinline__ void stage_tile(
    const float* __restrict__ Pre, const float* __restrict__ W,
    float* __restrict__ Asb, float* __restrict__ Wsb,
    int m0, int k0, int K, int tid) {
    constexpr int ASS = 128 + 4;
#pragma unroll
    for (int i = 0; i < 2; i++) {
        int idx = tid + i * 256;               // 0..511
        int row = idx >> 2;                    // 0..127
        int kf  = idx & 3;
        float4 v = *(const float4*)&Pre[(size_t)(m0 + row) * K + k0 + kf * 4];
        int kb = kf * 4;
        Asb[(kb + 0) * ASS + row] = v.x;
        Asb[(kb + 1) * ASS + row] = v.y;
        Asb[(kb + 2) * ASS + row] = v.z;
        Asb[(kb + 3) * ASS + row] = v.w;
    }
#pragma unroll
    for (int i = 0; i < 2; i++) {
        int idx = tid + i * 256;               // 0..511
        int kk = idx >> 5;                     // 0..15
        int cf = idx & 31;
        *(float4*)&Wsb[kk * 128 + cf * 4] =
            *(const float4*)&W[(size_t)(k0 + kk) * 128 + cf * 4];
    }
}

// --------------------- fused GEMM (N=128): out = [relu](Pre@W + b)[+res]
// BM=128, 256 threads, TM=8 x TN=8, f32x2 FMA, double-buffered smem pipeline.
template <int K>
__global__ void __launch_bounds__(256)
k_mlp128(const float* __restrict__ Pre, const float* __restrict__ W,
         const float* __restrict__ bias, const float* __restrict__ resid,
         float* __restrict__ out, int n, int do_relu) {
    constexpr int N = 128, KT = 16, TM = 8;
    constexpr int ASS = 128 + 4;
    constexpr int NT = K / KT;
    __shared__ float As[2][KT * ASS];
    __shared__ float Ws[2][KT * N];
    const int tid = threadIdx.x;                // 256
    const int tx = tid & 15;                    // col group: cols tx*8..+7
    const int ty = tid >> 4;                    // row group: rows ty*8..+7
    const int m0 = blockIdx.x * 128;

    unsigned long long acc[TM][4];
#pragma unroll
    for (int i = 0; i < TM; i++)
#pragma unroll
        for (int j = 0; j < 4; j++) acc[i][j] = 0ULL;

    stage_tile(Pre, W, As[0], Ws[0], m0, 0, K, tid);
    __syncthreads();

    for (int t = 0; t < NT; t++) {
        // prefetch next tile into the idle buffer (overlaps with compute)
        if (t + 1 < NT)
            stage_tile(Pre, W, As[(t + 1) & 1], Ws[(t + 1) & 1],
                       m0, (t + 1) * KT, K, tid);
        const float* Asb = As[t & 1];
        const float* Wsb = Ws[t & 1];
#pragma unroll
        for (int kk = 0; kk < KT; kk++) {
            float4 alo = *(const float4*)&Asb[kk * ASS + ty * TM];
            float4 ahi = *(const float4*)&Asb[kk * ASS + ty * TM + 4];
            float av[TM] = {alo.x, alo.y, alo.z, alo.w,
                            ahi.x, ahi.y, ahi.z, ahi.w};
            const ulonglong2* wp2 = (const ulonglong2*)&Wsb[kk * N + tx * 8];
            ulonglong2 w01 = wp2[0];
            ulonglong2 w23 = wp2[1];
            unsigned long long bpk[4] = {w01.x, w01.y, w23.x, w23.y};
#pragma unroll
            for (int i = 0; i < TM; i++) {
                unsigned int ab = __float_as_uint(av[i]);
                unsigned long long ap;
                asm("mov.b64 %0, {%1, %2};" : "=l"(ap) : "r"(ab), "r"(ab));
#pragma unroll
                for (int j = 0; j < 4; j++) {
                    asm("fma.rn.f32x2 %0, %1, %2, %0;"
                        : "+l"(acc[i][j]) : "l"(ap), "l"(bpk[j]));
                }
            }
        }
        __syncthreads();
    }

    // epilogue: bias -> relu -> residual -> store
#pragma unroll
    for (int i = 0; i < TM; i++) {
        int row = m0 + ty * TM + i;
        if (row >= n) continue;
#pragma unroll
        for (int j = 0; j < 4; j++) {
            unsigned int lo, hi;
            asm("mov.b64 {%0, %1}, %2;" : "=r"(lo), "=r"(hi) : "l"(acc[i][j]));
            int col = tx * 8 + j * 2;
            float v0 = __uint_as_float(lo) + bias[col];
            float v1 = __uint_as_float(hi) + bias[col + 1];
            if (do_relu) { v0 = fmaxf(v0, 0.f); v1 = fmaxf(v1, 0.f); }
            if (resid) {
                v0 += resid[(size_t)row * N + col];
                v1 += resid[(size_t)row * N + col + 1];
            }
            out[(size_t)row * N + col]     = v0;
            out[(size_t)row * N + col + 1] = v1;
        }
    }
}

// ------------------------------------- projection GEMM (N=32), scalar fp32
__global__ void __launch_bounds__(256)
k_proj(const float* __restrict__ Pre, const float* __restrict__ W,
       const float* __restrict__ bias, float* __restrict__ out, int n) {
    constexpr int K = 128, N = 32, BM = 64, KT = 32, TM = 4, TN = 2;
    constexpr int ASS = BM + 4;
    __shared__ float As[KT * ASS];
    __shared__ float Ws[KT * N];
    const int tid = threadIdx.x;
    const int tx = tid & 15;
    const int ty = tid >> 4;
    const int m0 = blockIdx.x * BM;

    float acc[TM][TN];
#pragma unroll
    for (int i = 0; i < TM; i++)
#pragma unroll
        for (int j = 0; j < TN; j++) acc[i][j] = 0.f;

    for (int k0 = 0; k0 < K; k0 += KT) {
        for (int i = tid; i < BM * (KT / 4); i += 256) {
            int row = i / (KT / 4), kf = i % (KT / 4);
            float4 v = *(const float4*)&Pre[(size_t)(m0 + row) * K + k0 + kf * 4];
            int kb = kf * 4;
            As[(kb + 0) * ASS + row] = v.x;
            As[(kb + 1) * ASS + row] = v.y;
            As[(kb + 2) * ASS + row] = v.z;
            As[(kb + 3) * ASS + row] = v.w;
        }
        for (int i = tid; i < KT * (N / 4); i += 256) {
            int kk = i / (N / 4), cf = i % (N / 4);
            *(float4*)&Ws[kk * N + cf * 4] =
                *(const float4*)&W[(size_t)(k0 + kk) * N + cf * 4];
        }
        __syncthreads();
#pragma unroll
        for (int kk = 0; kk < KT; kk++) {
            float4 a = *(const float4*)&As[kk * ASS + ty * TM];
            float av[TM] = {a.x, a.y, a.z, a.w};
            float bv[TN];
#pragma unroll
            for (int j = 0; j < TN; j++) bv[j] = Ws[kk * N + tx * TN + j];
#pragma unroll
            for (int i = 0; i < TM; i++)
#pragma unroll
                for (int j = 0; j < TN; j++) acc[i][j] += av[i] * bv[j];
        }
        __syncthreads();
    }
#pragma unroll
    for (int i = 0; i < TM; i++) {
        int row = m0 + ty * TM + i;
        if (row >= n) continue;
#pragma unroll
        for (int j = 0; j < TN; j++) {
            int col = tx * TN + j;
            out[(size_t)row * N + col] = acc[i][j] + bias[col];
        }
    }
}

// ---------------------------------------------------------------------------
extern "C" void kernel_launch(void* const* d_in, const int* in_sizes, int n_in,
                              void* d_out, int out_size) {
    const float* x  = (const float*)d_in[0];
    const void*  ei = d_in[1];
    const float* W0 = (const float*)d_in[2];
    const float* b0 = (const float*)d_in[3];
    const float* W1 = (const float*)d_in[4];
    const float* b1 = (const float*)d_in[5];
    const float* W2 = (const float*)d_in[6];
    const float* b2 = (const float*)d_in[7];
    const float* Wp = (const float*)d_in[8];
    const float* bp = (const float*)d_in[9];
    float* out = (float*)d_out;

    int n_nodes = in_sizes[0] / 64;          // IN_DIM = 64
    int n_edges = in_sizes[1] / 2;
    if (n_nodes > MAX_NODES_PAD) n_nodes = MAX_NODES_PAD;
    if (n_edges > MAX_EDGES)     n_edges = MAX_EDGES;

    float* pre;  cudaGetSymbolAddress((void**)&pre,  g_pre);
    float* bufA; cudaGetSymbolAddress((void**)&bufA, g_bufA);
    float* bufB; cudaGetSymbolAddress((void**)&bufB, g_bufB);
    int*   deg;  cudaGetSymbolAddress((void**)&deg,  g_deg);

    const int T = 256;
    cudaMemsetAsync(deg, 0, (size_t)n_nodes * sizeof(int));
    k_hist<<<(n_edges + T - 1) / T, T>>>(ei, n_edges);
    k_scan<<<1, 1024>>>(n_nodes);
    k_scatter<<<(n_edges + T - 1) / T, T>>>(ei, n_edges);

    const int agg64Blocks  = (n_nodes * 16 + 255) / 256;
    const int agg128Blocks = (n_nodes * 32 + 255) / 256;
    const int mlpBlocks    = (n_nodes + 127) / 128;
    const int projBlocks   = (n_nodes + 63) / 64;

    // layer 0: 64 -> 128, relu
    k_agg<64><<<agg64Blocks, 256>>>(x, pre, n_nodes);
    k_mlp128<64><<<mlpBlocks, 256>>>(pre, W0, b0, nullptr, bufA, n_nodes, 1);
    // layer 1: 128 -> 128, relu, residual bufA
    k_agg<128><<<agg128Blocks, 256>>>(bufA, pre, n_nodes);
    k_mlp128<128><<<mlpBlocks, 256>>>(pre, W1, b1, bufA, bufB, n_nodes, 1);
    // layer 2: 128 -> 128, relu, residual bufB
    k_agg<128><<<agg128Blocks, 256>>>(bufB, pre, n_nodes);
    k_mlp128<128><<<mlpBlocks, 256>>>(pre, W2, b2, bufB, bufA, n_nodes, 1);
    // projection: 128 -> 32
    k_proj<<<projBlocks, 256>>>(bufA, Wp, bp, out, n_nodes);
}